// round 12
// baseline (speedup 1.0000x reference)
#include <cuda_runtime.h>
#include <cuda_fp16.h>
#include <cstdint>

// R12: R11 + cp.async double-buffered weight staging (two WT buffers, staged
// one pass ahead; Wq hidden behind gather+LN, Wc behind attention). 8 syncs.
// smem 210944B, 1 CTA/SM (512 thr, 2 windows).

#define RSH  136   // halves stride for [64|128][128] fp16 buffers
#define RSV  72    // VbT [128][64] halves stride
#define TOK  64
#define CCH  128
#define VOLS 262144
#define WHALVES 35328   // per-window smem (halves): XW+XN+Kb+VbT
#define WTHALVES 17408  // one weight tile [128][136]

__device__ __half WH[5 * 16384];   // fp16 weights, [m][o][k] row-major

__global__ void prep_weights(const float* __restrict__ Win,
                             const float* __restrict__ Wout,
                             const float* __restrict__ Wc) {
    int idx = blockIdx.x * 256 + threadIdx.x;
    if (idx >= 5 * 16384) return;
    int m = idx >> 14, r = idx & 16383;
    float v;
    if (m < 3)       v = Win[(size_t)m * 16384 + r];
    else if (m == 3) v = Wout[r];
    else             v = Wc[r];
    WH[idx] = __float2half(v);
}

__device__ __forceinline__ uint32_t pkhf(float lo, float hi) {
    uint32_t r; asm("cvt.rn.f16x2.f32 %0, %1, %2;" : "=r"(r) : "f"(hi), "f"(lo));
    return r;
}
__device__ __forceinline__ float2 uphf(uint32_t v) {
    __half2 h; *(uint32_t*)&h = v;
    return __half22float2(h);
}
__device__ __forceinline__ uint32_t s2u(const void* p) {
    return (uint32_t)__cvta_generic_to_shared(p);
}
__device__ __forceinline__ void ldsm4(uint32_t& r0, uint32_t& r1,
                                      uint32_t& r2, uint32_t& r3, uint32_t addr) {
    asm volatile("ldmatrix.sync.aligned.m8n8.x4.shared.b16 {%0,%1,%2,%3}, [%4];"
                 : "=r"(r0), "=r"(r1), "=r"(r2), "=r"(r3) : "r"(addr));
}
__device__ __forceinline__ void mma16(float c[4], uint32_t a0, uint32_t a1,
                                      uint32_t a2, uint32_t a3,
                                      uint32_t b0, uint32_t b1) {
    asm volatile("mma.sync.aligned.m16n8k16.row.col.f32.f16.f16.f32 "
                 "{%0,%1,%2,%3}, {%4,%5,%6,%7}, {%8,%9}, {%0,%1,%2,%3};"
                 : "+f"(c[0]), "+f"(c[1]), "+f"(c[2]), "+f"(c[3])
                 : "r"(a0), "r"(a1), "r"(a2), "r"(a3), "r"(b0), "r"(b1));
}
__device__ __forceinline__ void cpa16(uint32_t dst, const void* src) {
    asm volatile("cp.async.cg.shared.global [%0], [%1], 16;"
                 :: "r"(dst), "l"(src));
}
// Stage one 128x128 fp16 weight matrix into WT via cp.async (4 ops/thread).
__device__ __forceinline__ void stageW(__half* WT, const __half* src, int tid) {
    for (int e = tid; e < 2048; e += 512) {
        int o = e >> 4, k8 = e & 15;
        cpa16(s2u(WT + o * RSH + k8 * 8), src + o * 128 + k8 * 8);
    }
    asm volatile("cp.async.commit_group;" ::: "memory");
}
#define CPA_WAIT0() asm volatile("cp.async.wait_group 0;" ::: "memory")

// Warp tile rows [r0,r0+32) x cols [c0,c0+32) of A * B^T, both smem, ldmatrix.
template<int KK>
__device__ __forceinline__ void gemm32(const __half* __restrict__ A, int ras,
                                       const __half* __restrict__ B, int rbs,
                                       int r0, int c0, int lane,
                                       float C[2][4][4]) {
#pragma unroll
    for (int i = 0; i < 2; i++)
#pragma unroll
        for (int j = 0; j < 4; j++)
#pragma unroll
            for (int q = 0; q < 4; q++) C[i][j][q] = 0.f;
    uint32_t aaddr[2], baddr[2];
#pragma unroll
    for (int i = 0; i < 2; i++)
        aaddr[i] = s2u(A + (r0 + 16 * i + (lane & 15)) * ras + ((lane >> 4) << 3));
#pragma unroll
    for (int p = 0; p < 2; p++)
        baddr[p] = s2u(B + (c0 + 16 * p + (lane & 7) + ((lane >> 4) << 3)) * rbs
                         + (((lane >> 3) & 1) << 3));
#pragma unroll
    for (int s = 0; s < KK / 16; s++) {
        uint32_t a[2][4];
#pragma unroll
        for (int i = 0; i < 2; i++)
            ldsm4(a[i][0], a[i][1], a[i][2], a[i][3], aaddr[i] + s * 32);
#pragma unroll
        for (int p = 0; p < 2; p++) {
            uint32_t b00, b10, b01, b11;
            ldsm4(b00, b10, b01, b11, baddr[p] + s * 32);
#pragma unroll
            for (int i = 0; i < 2; i++) {
                mma16(C[i][2 * p],     a[i][0], a[i][1], a[i][2], a[i][3], b00, b10);
                mma16(C[i][2 * p + 1], a[i][0], a[i][1], a[i][2], a[i][3], b01, b11);
            }
        }
    }
}

__global__ __launch_bounds__(512, 1)
void win_attn_kernel(const float* __restrict__ x,
                     const float* __restrict__ ln_g, const float* __restrict__ ln_b,
                     const float* __restrict__ bin,
                     const float* __restrict__ bout,
                     const float* __restrict__ bc,
                     float* __restrict__ out) {
    extern __shared__ char smbase[];
    const int tid  = threadIdx.x;
    const int wsel = tid >> 8;          // which of the 2 windows
    const int ltid = tid & 255;
    const int w8   = (tid >> 5) & 7;
    const int lane = tid & 31;
    const int g = lane >> 2, t = lane & 3;
    const int r0 = (w8 & 1) * 32;
    const int c0 = (w8 >> 1) * 32;
    const int hh = w8 >> 1;

    __half* XW  = (__half*)smbase + wsel * WHALVES;  // [64][136] x fp16
    __half* XN  = XW  + TOK * RSH;                   // [64][136] LN -> o -> conv
    __half* Kb  = XN  + TOK * RSH;                   // [64][136] k -> y
    __half* VbT = Kb  + TOK * RSH;                   // [128][72] V^T
    __half* WT0 = (__half*)smbase + 2 * WHALVES;     // [128][136] weight buf 0
    __half* WT1 = WT0 + WTHALVES;                    // [128][136] weight buf 1

    const int wid = blockIdx.x * 2 + wsel;
    const int bb  = wid >> 12;
    const int rr  = wid & 4095;
    const int vd0 = (rr >> 8) * 4;
    const int vh0 = ((rr >> 4) & 15) * 4;
    const int vw0 = (rr & 15) * 4;
    const float* xb = x + (size_t)bb * ((size_t)CCH * VOLS);
    const size_t vox0 = (size_t)vd0 * 4096 + (size_t)vh0 * 64 + vw0;

    const int c0l = ltid & 31, tq0 = ltid >> 5;

    // ---- stage Wq early (hidden behind gather + LN) ----
    stageW(WT0, WH, tid);

    // ---- gather window into XW (fp16) ----
#pragma unroll
    for (int i = 0; i < 8; i++) {
        int c  = c0l + 32 * (i & 3);
        int tq = tq0 + 8 * (i >> 2);
        int dz = tq >> 2, dy = tq & 3;
        float4 v = *(const float4*)(xb + (size_t)c * VOLS + vox0 + dz * 4096 + dy * 64);
        __half* dst = XW + (tq * 4) * RSH + c;
        dst[0]       = __float2half(v.x);
        dst[RSH]     = __float2half(v.y);
        dst[2 * RSH] = __float2half(v.z);
        dst[3 * RSH] = __float2half(v.w);
    }
    __syncthreads();

    // ---- LayerNorm XW -> XN (4 threads/token) ----
    {
        int tt = ltid >> 2, sub = ltid & 3;
        const __half* row = XW + tt * RSH;
        float s = 0.f, ss = 0.f;
        float2 vals[16];
#pragma unroll
        for (int i = 0; i < 16; i++) {
            float2 v = uphf(*(const uint32_t*)(row + 2 * sub + 8 * i));
            vals[i] = v;
            s += v.x + v.y; ss += v.x * v.x + v.y * v.y;
        }
        s  += __shfl_xor_sync(0xffffffffu, s, 1);  s  += __shfl_xor_sync(0xffffffffu, s, 2);
        ss += __shfl_xor_sync(0xffffffffu, ss, 1); ss += __shfl_xor_sync(0xffffffffu, ss, 2);
        float mu = s * (1.f / 128.f);
        float var = ss * (1.f / 128.f) - mu * mu;
        float rstd = rsqrtf(var + 1e-5f);
        __half* nrow = XN + tt * RSH;
#pragma unroll
        for (int i = 0; i < 16; i++) {
            int c = 2 * sub + 8 * i;
            float2 gl = *(const float2*)(ln_g + c);
            float2 bl = *(const float2*)(ln_b + c);
            *(uint32_t*)(nrow + c) = pkhf((vals[i].x - mu) * rstd * gl.x + bl.x,
                                          (vals[i].y - mu) * rstd * gl.y + bl.y);
        }
    }
    CPA_WAIT0();
    __syncthreads();   // XN ready + Wq in WT0

    uint32_t qf[2][2][4];   // Q A-fragments in registers

    // ---- 3 QKV passes; next weights staged DURING each gemm ----
    for (int p = 0; p < 3; p++) {
        __half* WTc = (p & 1) ? WT1 : WT0;
        __half* WTn = (p & 1) ? WT0 : WT1;
        stageW(WTn, WH + (p + 1) * 16384, tid);   // Wk / Wv / Wout ahead
        float C[2][4][4];
        gemm32<128>(XN, RSH, WTc, RSH, r0, c0, lane, C);
        if (p == 0) {
#pragma unroll
            for (int i = 0; i < 2; i++)
#pragma unroll
                for (int s = 0; s < 2; s++) {
                    float2 bA = *(const float2*)(bin + c0 + 16 * s + 2 * t);
                    float2 bB = *(const float2*)(bin + c0 + 16 * s + 8 + 2 * t);
                    qf[i][s][0] = pkhf(C[i][2*s][0] + bA.x, C[i][2*s][1] + bA.y);
                    qf[i][s][1] = pkhf(C[i][2*s][2] + bA.x, C[i][2*s][3] + bA.y);
                    qf[i][s][2] = pkhf(C[i][2*s+1][0] + bB.x, C[i][2*s+1][1] + bB.y);
                    qf[i][s][3] = pkhf(C[i][2*s+1][2] + bB.x, C[i][2*s+1][3] + bB.y);
                }
        } else if (p == 1) {
#pragma unroll
            for (int i = 0; i < 2; i++) {
                int ra = r0 + 16 * i + g;
#pragma unroll
                for (int j = 0; j < 4; j++) {
                    int cl = c0 + 8 * j + 2 * t;
                    float2 b2 = *(const float2*)(bin + 128 + cl);
                    *(uint32_t*)(Kb + ra * RSH + cl) =
                        pkhf(C[i][j][0] + b2.x, C[i][j][1] + b2.y);
                    *(uint32_t*)(Kb + (ra + 8) * RSH + cl) =
                        pkhf(C[i][j][2] + b2.x, C[i][j][3] + b2.y);
                }
            }
        } else {
#pragma unroll
            for (int i = 0; i < 2; i++) {
                int ra = r0 + 16 * i + g;
#pragma unroll
                for (int j = 0; j < 4; j++) {
                    int cl = c0 + 8 * j + 2 * t;
                    float2 b2 = *(const float2*)(bin + 256 + cl);
                    VbT[(cl    ) * RSV + ra]     = __float2half(C[i][j][0] + b2.x);
                    VbT[(cl + 1) * RSV + ra]     = __float2half(C[i][j][1] + b2.y);
                    VbT[(cl    ) * RSV + ra + 8] = __float2half(C[i][j][2] + b2.x);
                    VbT[(cl + 1) * RSV + ra + 8] = __float2half(C[i][j][3] + b2.y);
                }
            }
        }
        CPA_WAIT0();
        __syncthreads();
    }
    // here: K,V visible; Wout in WT1 (staged during p=2)

    // ---- stage Wc during register-resident attention ----
    stageW(WT0, WH + 4 * 16384, tid);

    // ---- attention, fully in registers: scores -> softmax -> P -> AV ----
    {
        const float sc_norm = 0.17677669529663687f; // 1/sqrt(32)
        float E[2][8][4];
#pragma unroll
        for (int i = 0; i < 2; i++)
#pragma unroll
            for (int j = 0; j < 8; j++)
#pragma unroll
                for (int q = 0; q < 4; q++) E[i][j][q] = 0.f;
        uint32_t kaddr[4];
#pragma unroll
        for (int p = 0; p < 4; p++)
            kaddr[p] = s2u(Kb + (16 * p + (lane & 7) + ((lane >> 4) << 3)) * RSH
                             + hh * 32 + (((lane >> 3) & 1) << 3));
#pragma unroll
        for (int s = 0; s < 2; s++)
#pragma unroll
            for (int p = 0; p < 4; p++) {
                uint32_t b00, b10, b01, b11;
                ldsm4(b00, b10, b01, b11, kaddr[p] + s * 32);
#pragma unroll
                for (int i = 0; i < 2; i++) {
                    mma16(E[i][2*p],   qf[i][s][0], qf[i][s][1], qf[i][s][2], qf[i][s][3], b00, b10);
                    mma16(E[i][2*p+1], qf[i][s][0], qf[i][s][1], qf[i][s][2], qf[i][s][3], b01, b11);
                }
            }
        float rs[2][2] = {{0.f, 0.f}, {0.f, 0.f}};
#pragma unroll
        for (int i = 0; i < 2; i++)
#pragma unroll
            for (int j = 0; j < 8; j++)
#pragma unroll
                for (int q = 0; q < 4; q++) {
                    float sv = E[i][j][q] * sc_norm;
                    float r = fmaf(1.f/120.f, sv, 1.f/24.f);
                    r = fmaf(r, sv, 1.f/6.f);
                    r = fmaf(r, sv, 0.5f);
                    r = fmaf(r, sv, 1.f);
                    r = fmaf(r, sv, 1.f);
                    E[i][j][q] = r;
                    rs[i][q >> 1] += r;
                }
#pragma unroll
        for (int i = 0; i < 2; i++)
#pragma unroll
            for (int h2 = 0; h2 < 2; h2++) {
                float s = rs[i][h2];
                s += __shfl_xor_sync(0xffffffffu, s, 1);
                s += __shfl_xor_sync(0xffffffffu, s, 2);
                rs[i][h2] = __frcp_rn(s);
            }
        uint32_t pf[2][4][4];
#pragma unroll
        for (int i = 0; i < 2; i++)
#pragma unroll
            for (int s = 0; s < 4; s++) {
                pf[i][s][0] = pkhf(E[i][2*s][0]   * rs[i][0], E[i][2*s][1]   * rs[i][0]);
                pf[i][s][1] = pkhf(E[i][2*s][2]   * rs[i][1], E[i][2*s][3]   * rs[i][1]);
                pf[i][s][2] = pkhf(E[i][2*s+1][0] * rs[i][0], E[i][2*s+1][1] * rs[i][0]);
                pf[i][s][3] = pkhf(E[i][2*s+1][2] * rs[i][1], E[i][2*s+1][3] * rs[i][1]);
            }
        uint32_t vaddr[2];
#pragma unroll
        for (int p = 0; p < 2; p++)
            vaddr[p] = s2u(VbT + (hh * 32 + 16 * p + (lane & 7) + ((lane >> 4) << 3)) * RSV
                             + (((lane >> 3) & 1) << 3));
        float Co[2][4][4];
#pragma unroll
        for (int i = 0; i < 2; i++)
#pragma unroll
            for (int j = 0; j < 4; j++)
#pragma unroll
                for (int q = 0; q < 4; q++) Co[i][j][q] = 0.f;
#pragma unroll
        for (int s = 0; s < 4; s++)
#pragma unroll
            for (int p = 0; p < 2; p++) {
                uint32_t b00, b10, b01, b11;
                ldsm4(b00, b10, b01, b11, vaddr[p] + s * 32);
#pragma unroll
                for (int i = 0; i < 2; i++) {
                    mma16(Co[i][2*p],   pf[i][s][0], pf[i][s][1], pf[i][s][2], pf[i][s][3], b00, b10);
                    mma16(Co[i][2*p+1], pf[i][s][0], pf[i][s][1], pf[i][s][2], pf[i][s][3], b01, b11);
                }
            }
#pragma unroll
        for (int i = 0; i < 2; i++) {
            int ra = r0 + 16 * i + g;
#pragma unroll
            for (int j = 0; j < 4; j++) {
                int cl = hh * 32 + 8 * j + 2 * t;
                *(uint32_t*)(XN + ra * RSH + cl)       = pkhf(Co[i][j][0], Co[i][j][1]);
                *(uint32_t*)(XN + (ra + 8) * RSH + cl) = pkhf(Co[i][j][2], Co[i][j][3]);
            }
        }
    }
    CPA_WAIT0();
    __syncthreads();   // o in XN + Wout in WT1 + Wc in WT0

    // ---- out_proj: y = xw + o @ Wout^T + bout -> Kb ----
    {
        float C[2][4][4];
        gemm32<128>(XN, RSH, WT1, RSH, r0, c0, lane, C);
#pragma unroll
        for (int i = 0; i < 2; i++) {
            int ra = r0 + 16 * i + g;
#pragma unroll
            for (int j = 0; j < 4; j++) {
                int cl = c0 + 8 * j + 2 * t;
                float2 b2 = *(const float2*)(bout + cl);
                float2 xw0 = uphf(*(const uint32_t*)(XW + ra * RSH + cl));
                float2 xw1 = uphf(*(const uint32_t*)(XW + (ra + 8) * RSH + cl));
                *(uint32_t*)(Kb + ra * RSH + cl) =
                    pkhf(C[i][j][0] + b2.x + xw0.x, C[i][j][1] + b2.y + xw0.y);
                *(uint32_t*)(Kb + (ra + 8) * RSH + cl) =
                    pkhf(C[i][j][2] + b2.x + xw1.x, C[i][j][3] + b2.y + xw1.y);
            }
        }
    }
    __syncthreads();

    // ---- conv: Kb @ Wc^T + bc -> XN (fp16) ----
    {
        float C[2][4][4];
        gemm32<128>(Kb, RSH, WT0, RSH, r0, c0, lane, C);
#pragma unroll
        for (int i = 0; i < 2; i++) {
            int ra = r0 + 16 * i + g;
#pragma unroll
            for (int j = 0; j < 4; j++) {
                int cl = c0 + 8 * j + 2 * t;
                float2 b2 = *(const float2*)(bc + cl);
                *(uint32_t*)(XN + ra * RSH + cl) =
                    pkhf(C[i][j][0] + b2.x, C[i][j][1] + b2.y);
                *(uint32_t*)(XN + (ra + 8) * RSH + cl) =
                    pkhf(C[i][j][2] + b2.x, C[i][j][3] + b2.y);
            }
        }
    }
    __syncthreads();

    // ---- epilogue: out = conv(fp16) + x (exact fp32), coalesced ----
    float* outp = out + (size_t)bb * ((size_t)CCH * VOLS);
#pragma unroll
    for (int i = 0; i < 8; i++) {
        int c  = c0l + 32 * (i & 3);
        int tq = tq0 + 8 * (i >> 2);
        int dz = tq >> 2, dy = tq & 3;
        size_t gaddr = (size_t)c * VOLS + vox0 + dz * 4096 + dy * 64;
        float4 xv = *(const float4*)(xb + gaddr);
        const __half* src = XN + (tq * 4) * RSH + c;
        float4 v = { __half2float(src[0])       + xv.x,
                     __half2float(src[RSH])     + xv.y,
                     __half2float(src[2 * RSH]) + xv.z,
                     __half2float(src[3 * RSH]) + xv.w };
        *(float4*)(outp + gaddr) = v;
    }
}

// 2 windows x 35328 + 2 x 17408 = 105472 halves -> 210944 B
static const int SMEM_BYTES = 210944;

extern "C" void kernel_launch(void* const* d_in, const int* in_sizes, int n_in,
                              void* d_out, int out_size) {
    const float* x    = (const float*)d_in[0];
    const float* ln_g = (const float*)d_in[1];
    const float* ln_b = (const float*)d_in[2];
    const float* Win  = (const float*)d_in[3];
    const float* bin  = (const float*)d_in[4];
    const float* Wout = (const float*)d_in[5];
    const float* bout = (const float*)d_in[6];
    const float* Wc   = (const float*)d_in[7];
    const float* bc   = (const float*)d_in[8];
    float* out = (float*)d_out;

    prep_weights<<<320, 256>>>(Win, Wout, Wc);

    cudaFuncSetAttribute(win_attn_kernel,
                         cudaFuncAttributeMaxDynamicSharedMemorySize, SMEM_BYTES);
    win_attn_kernel<<<4096, 512, SMEM_BYTES>>>(x, ln_g, ln_b, bin, bout, bc, out);
}

// round 13
// speedup vs baseline: 1.0106x; 1.0106x over previous
#include <cuda_runtime.h>
#include <cuda_fp16.h>
#include <cstdint>

// R13: R12 + software-pipelined operand loads (double-buffered ldsm frags in
// gemm32; depth-1 prefetch in attention) to break ldsm->mma latency chains.

#define RSH  136   // halves stride for [64|128][128] fp16 buffers
#define RSV  72    // VbT [128][64] halves stride
#define TOK  64
#define CCH  128
#define VOLS 262144
#define WHALVES 35328   // per-window smem (halves): XW+XN+Kb+VbT
#define WTHALVES 17408  // one weight tile [128][136]

__device__ __half WH[5 * 16384];   // fp16 weights, [m][o][k] row-major

__global__ void prep_weights(const float* __restrict__ Win,
                             const float* __restrict__ Wout,
                             const float* __restrict__ Wc) {
    int idx = blockIdx.x * 256 + threadIdx.x;
    if (idx >= 5 * 16384) return;
    int m = idx >> 14, r = idx & 16383;
    float v;
    if (m < 3)       v = Win[(size_t)m * 16384 + r];
    else if (m == 3) v = Wout[r];
    else             v = Wc[r];
    WH[idx] = __float2half(v);
}

__device__ __forceinline__ uint32_t pkhf(float lo, float hi) {
    uint32_t r; asm("cvt.rn.f16x2.f32 %0, %1, %2;" : "=r"(r) : "f"(hi), "f"(lo));
    return r;
}
__device__ __forceinline__ float2 uphf(uint32_t v) {
    __half2 h; *(uint32_t*)&h = v;
    return __half22float2(h);
}
__device__ __forceinline__ uint32_t s2u(const void* p) {
    return (uint32_t)__cvta_generic_to_shared(p);
}
__device__ __forceinline__ void ldsm4(uint32_t& r0, uint32_t& r1,
                                      uint32_t& r2, uint32_t& r3, uint32_t addr) {
    asm volatile("ldmatrix.sync.aligned.m8n8.x4.shared.b16 {%0,%1,%2,%3}, [%4];"
                 : "=r"(r0), "=r"(r1), "=r"(r2), "=r"(r3) : "r"(addr));
}
__device__ __forceinline__ void mma16(float c[4], uint32_t a0, uint32_t a1,
                                      uint32_t a2, uint32_t a3,
                                      uint32_t b0, uint32_t b1) {
    asm volatile("mma.sync.aligned.m16n8k16.row.col.f32.f16.f16.f32 "
                 "{%0,%1,%2,%3}, {%4,%5,%6,%7}, {%8,%9}, {%0,%1,%2,%3};"
                 : "+f"(c[0]), "+f"(c[1]), "+f"(c[2]), "+f"(c[3])
                 : "r"(a0), "r"(a1), "r"(a2), "r"(a3), "r"(b0), "r"(b1));
}
__device__ __forceinline__ void cpa16(uint32_t dst, const void* src) {
    asm volatile("cp.async.cg.shared.global [%0], [%1], 16;"
                 :: "r"(dst), "l"(src));
}
__device__ __forceinline__ void stageW(__half* WT, const __half* src, int tid) {
    for (int e = tid; e < 2048; e += 512) {
        int o = e >> 4, k8 = e & 15;
        cpa16(s2u(WT + o * RSH + k8 * 8), src + o * 128 + k8 * 8);
    }
    asm volatile("cp.async.commit_group;" ::: "memory");
}
#define CPA_WAIT0() asm volatile("cp.async.wait_group 0;" ::: "memory")

// Software-pipelined warp-tile GEMM: rows [r0,r0+32) x cols [c0,c0+32).
// Double-buffered a/b fragments: step s+1's ldsm issued before step s's mmas.
template<int KK>
__device__ __forceinline__ void gemm32(const __half* __restrict__ A, int ras,
                                       const __half* __restrict__ B, int rbs,
                                       int r0, int c0, int lane,
                                       float C[2][4][4]) {
    constexpr int NS = KK / 16;
#pragma unroll
    for (int i = 0; i < 2; i++)
#pragma unroll
        for (int j = 0; j < 4; j++)
#pragma unroll
            for (int q = 0; q < 4; q++) C[i][j][q] = 0.f;
    uint32_t aaddr[2], baddr[2];
#pragma unroll
    for (int i = 0; i < 2; i++)
        aaddr[i] = s2u(A + (r0 + 16 * i + (lane & 15)) * ras + ((lane >> 4) << 3));
#pragma unroll
    for (int p = 0; p < 2; p++)
        baddr[p] = s2u(B + (c0 + 16 * p + (lane & 7) + ((lane >> 4) << 3)) * rbs
                         + (((lane >> 3) & 1) << 3));
    uint32_t a[2][2][4], b[2][2][4];   // [buf][frag][4]
    ldsm4(a[0][0][0], a[0][0][1], a[0][0][2], a[0][0][3], aaddr[0]);
    ldsm4(a[0][1][0], a[0][1][1], a[0][1][2], a[0][1][3], aaddr[1]);
    ldsm4(b[0][0][0], b[0][0][1], b[0][0][2], b[0][0][3], baddr[0]);
    ldsm4(b[0][1][0], b[0][1][1], b[0][1][2], b[0][1][3], baddr[1]);
#pragma unroll
    for (int s = 0; s < NS; s++) {
        const int cur = s & 1, nxt = cur ^ 1;
        if (s + 1 < NS) {
            ldsm4(a[nxt][0][0], a[nxt][0][1], a[nxt][0][2], a[nxt][0][3],
                  aaddr[0] + (s + 1) * 32);
            ldsm4(a[nxt][1][0], a[nxt][1][1], a[nxt][1][2], a[nxt][1][3],
                  aaddr[1] + (s + 1) * 32);
            ldsm4(b[nxt][0][0], b[nxt][0][1], b[nxt][0][2], b[nxt][0][3],
                  baddr[0] + (s + 1) * 32);
            ldsm4(b[nxt][1][0], b[nxt][1][1], b[nxt][1][2], b[nxt][1][3],
                  baddr[1] + (s + 1) * 32);
        }
#pragma unroll
        for (int p = 0; p < 2; p++)
#pragma unroll
            for (int i = 0; i < 2; i++) {
                mma16(C[i][2 * p], a[cur][i][0], a[cur][i][1], a[cur][i][2],
                      a[cur][i][3], b[cur][p][0], b[cur][p][1]);
                mma16(C[i][2 * p + 1], a[cur][i][0], a[cur][i][1], a[cur][i][2],
                      a[cur][i][3], b[cur][p][2], b[cur][p][3]);
            }
    }
}

__global__ __launch_bounds__(512, 1)
void win_attn_kernel(const float* __restrict__ x,
                     const float* __restrict__ ln_g, const float* __restrict__ ln_b,
                     const float* __restrict__ bin,
                     const float* __restrict__ bout,
                     const float* __restrict__ bc,
                     float* __restrict__ out) {
    extern __shared__ char smbase[];
    const int tid  = threadIdx.x;
    const int wsel = tid >> 8;
    const int ltid = tid & 255;
    const int w8   = (tid >> 5) & 7;
    const int lane = tid & 31;
    const int g = lane >> 2, t = lane & 3;
    const int r0 = (w8 & 1) * 32;
    const int c0 = (w8 >> 1) * 32;
    const int hh = w8 >> 1;

    __half* XW  = (__half*)smbase + wsel * WHALVES;
    __half* XN  = XW  + TOK * RSH;
    __half* Kb  = XN  + TOK * RSH;
    __half* VbT = Kb  + TOK * RSH;
    __half* WT0 = (__half*)smbase + 2 * WHALVES;
    __half* WT1 = WT0 + WTHALVES;

    const int wid = blockIdx.x * 2 + wsel;
    const int bb  = wid >> 12;
    const int rr  = wid & 4095;
    const int vd0 = (rr >> 8) * 4;
    const int vh0 = ((rr >> 4) & 15) * 4;
    const int vw0 = (rr & 15) * 4;
    const float* xb = x + (size_t)bb * ((size_t)CCH * VOLS);
    const size_t vox0 = (size_t)vd0 * 4096 + (size_t)vh0 * 64 + vw0;

    const int c0l = ltid & 31, tq0 = ltid >> 5;

    // ---- stage Wq early (hidden behind gather + LN) ----
    stageW(WT0, WH, tid);

    // ---- gather window into XW (fp16) ----
#pragma unroll
    for (int i = 0; i < 8; i++) {
        int c  = c0l + 32 * (i & 3);
        int tq = tq0 + 8 * (i >> 2);
        int dz = tq >> 2, dy = tq & 3;
        float4 v = *(const float4*)(xb + (size_t)c * VOLS + vox0 + dz * 4096 + dy * 64);
        __half* dst = XW + (tq * 4) * RSH + c;
        dst[0]       = __float2half(v.x);
        dst[RSH]     = __float2half(v.y);
        dst[2 * RSH] = __float2half(v.z);
        dst[3 * RSH] = __float2half(v.w);
    }
    __syncthreads();

    // ---- LayerNorm XW -> XN ----
    {
        int tt = ltid >> 2, sub = ltid & 3;
        const __half* row = XW + tt * RSH;
        float s = 0.f, ss = 0.f;
        float2 vals[16];
#pragma unroll
        for (int i = 0; i < 16; i++) {
            float2 v = uphf(*(const uint32_t*)(row + 2 * sub + 8 * i));
            vals[i] = v;
            s += v.x + v.y; ss += v.x * v.x + v.y * v.y;
        }
        s  += __shfl_xor_sync(0xffffffffu, s, 1);  s  += __shfl_xor_sync(0xffffffffu, s, 2);
        ss += __shfl_xor_sync(0xffffffffu, ss, 1); ss += __shfl_xor_sync(0xffffffffu, ss, 2);
        float mu = s * (1.f / 128.f);
        float var = ss * (1.f / 128.f) - mu * mu;
        float rstd = rsqrtf(var + 1e-5f);
        __half* nrow = XN + tt * RSH;
#pragma unroll
        for (int i = 0; i < 16; i++) {
            int c = 2 * sub + 8 * i;
            float2 gl = *(const float2*)(ln_g + c);
            float2 bl = *(const float2*)(ln_b + c);
            *(uint32_t*)(nrow + c) = pkhf((vals[i].x - mu) * rstd * gl.x + bl.x,
                                          (vals[i].y - mu) * rstd * gl.y + bl.y);
        }
    }
    CPA_WAIT0();
    __syncthreads();

    uint32_t qf[2][2][4];

    // ---- 3 QKV passes; next weights staged during each gemm ----
    for (int p = 0; p < 3; p++) {
        __half* WTc = (p & 1) ? WT1 : WT0;
        __half* WTn = (p & 1) ? WT0 : WT1;
        stageW(WTn, WH + (p + 1) * 16384, tid);
        float C[2][4][4];
        gemm32<128>(XN, RSH, WTc, RSH, r0, c0, lane, C);
        if (p == 0) {
#pragma unroll
            for (int i = 0; i < 2; i++)
#pragma unroll
                for (int s = 0; s < 2; s++) {
                    float2 bA = *(const float2*)(bin + c0 + 16 * s + 2 * t);
                    float2 bB = *(const float2*)(bin + c0 + 16 * s + 8 + 2 * t);
                    qf[i][s][0] = pkhf(C[i][2*s][0] + bA.x, C[i][2*s][1] + bA.y);
                    qf[i][s][1] = pkhf(C[i][2*s][2] + bA.x, C[i][2*s][3] + bA.y);
                    qf[i][s][2] = pkhf(C[i][2*s+1][0] + bB.x, C[i][2*s+1][1] + bB.y);
                    qf[i][s][3] = pkhf(C[i][2*s+1][2] + bB.x, C[i][2*s+1][3] + bB.y);
                }
        } else if (p == 1) {
#pragma unroll
            for (int i = 0; i < 2; i++) {
                int ra = r0 + 16 * i + g;
#pragma unroll
                for (int j = 0; j < 4; j++) {
                    int cl = c0 + 8 * j + 2 * t;
                    float2 b2 = *(const float2*)(bin + 128 + cl);
                    *(uint32_t*)(Kb + ra * RSH + cl) =
                        pkhf(C[i][j][0] + b2.x, C[i][j][1] + b2.y);
                    *(uint32_t*)(Kb + (ra + 8) * RSH + cl) =
                        pkhf(C[i][j][2] + b2.x, C[i][j][3] + b2.y);
                }
            }
        } else {
#pragma unroll
            for (int i = 0; i < 2; i++) {
                int ra = r0 + 16 * i + g;
#pragma unroll
                for (int j = 0; j < 4; j++) {
                    int cl = c0 + 8 * j + 2 * t;
                    float2 b2 = *(const float2*)(bin + 256 + cl);
                    VbT[(cl    ) * RSV + ra]     = __float2half(C[i][j][0] + b2.x);
                    VbT[(cl + 1) * RSV + ra]     = __float2half(C[i][j][1] + b2.y);
                    VbT[(cl    ) * RSV + ra + 8] = __float2half(C[i][j][2] + b2.x);
                    VbT[(cl + 1) * RSV + ra + 8] = __float2half(C[i][j][3] + b2.y);
                }
            }
        }
        CPA_WAIT0();
        __syncthreads();
    }

    // ---- stage Wc during register-resident attention ----
    stageW(WT0, WH + 4 * 16384, tid);

    // ---- attention in registers, depth-1 ldsm prefetch ----
    {
        const float sc_norm = 0.17677669529663687f;
        float E[2][8][4];
#pragma unroll
        for (int i = 0; i < 2; i++)
#pragma unroll
            for (int j = 0; j < 8; j++)
#pragma unroll
                for (int q = 0; q < 4; q++) E[i][j][q] = 0.f;
        uint32_t kaddr[4];
#pragma unroll
        for (int p = 0; p < 4; p++)
            kaddr[p] = s2u(Kb + (16 * p + (lane & 7) + ((lane >> 4) << 3)) * RSH
                             + hh * 32 + (((lane >> 3) & 1) << 3));
        // scores: 8 steps u = s*4+p, double-buffered b frags
        {
            uint32_t bq[2][4];
            ldsm4(bq[0][0], bq[0][1], bq[0][2], bq[0][3], kaddr[0]);
#pragma unroll
            for (int u = 0; u < 8; u++) {
                const int cur = u & 1, nxt = cur ^ 1;
                if (u + 1 < 8) {
                    int s1 = (u + 1) >> 2, p1 = (u + 1) & 3;
                    ldsm4(bq[nxt][0], bq[nxt][1], bq[nxt][2], bq[nxt][3],
                          kaddr[p1] + s1 * 32);
                }
                const int s = u >> 2, p = u & 3;
#pragma unroll
                for (int i = 0; i < 2; i++) {
                    mma16(E[i][2*p],   qf[i][s][0], qf[i][s][1], qf[i][s][2],
                          qf[i][s][3], bq[cur][0], bq[cur][1]);
                    mma16(E[i][2*p+1], qf[i][s][0], qf[i][s][1], qf[i][s][2],
                          qf[i][s][3], bq[cur][2], bq[cur][3]);
                }
            }
        }
        float rs[2][2] = {{0.f, 0.f}, {0.f, 0.f}};
#pragma unroll
        for (int i = 0; i < 2; i++)
#pragma unroll
            for (int j = 0; j < 8; j++)
#pragma unroll
                for (int q = 0; q < 4; q++) {
                    float sv = E[i][j][q] * sc_norm;
                    float r = fmaf(1.f/120.f, sv, 1.f/24.f);
                    r = fmaf(r, sv, 1.f/6.f);
                    r = fmaf(r, sv, 0.5f);
                    r = fmaf(r, sv, 1.f);
                    r = fmaf(r, sv, 1.f);
                    E[i][j][q] = r;
                    rs[i][q >> 1] += r;
                }
#pragma unroll
        for (int i = 0; i < 2; i++)
#pragma unroll
            for (int h2 = 0; h2 < 2; h2++) {
                float s = rs[i][h2];
                s += __shfl_xor_sync(0xffffffffu, s, 1);
                s += __shfl_xor_sync(0xffffffffu, s, 2);
                rs[i][h2] = __frcp_rn(s);
            }
        uint32_t pf[2][4][4];
#pragma unroll
        for (int i = 0; i < 2; i++)
#pragma unroll
            for (int s = 0; s < 4; s++) {
                pf[i][s][0] = pkhf(E[i][2*s][0]   * rs[i][0], E[i][2*s][1]   * rs[i][0]);
                pf[i][s][1] = pkhf(E[i][2*s][2]   * rs[i][1], E[i][2*s][3]   * rs[i][1]);
                pf[i][s][2] = pkhf(E[i][2*s+1][0] * rs[i][0], E[i][2*s+1][1] * rs[i][0]);
                pf[i][s][3] = pkhf(E[i][2*s+1][2] * rs[i][1], E[i][2*s+1][3] * rs[i][1]);
            }
        uint32_t vaddr[2];
#pragma unroll
        for (int p = 0; p < 2; p++)
            vaddr[p] = s2u(VbT + (hh * 32 + 16 * p + (lane & 7) + ((lane >> 4) << 3)) * RSV
                             + (((lane >> 3) & 1) << 3));
        float Co[2][4][4];
#pragma unroll
        for (int i = 0; i < 2; i++)
#pragma unroll
            for (int j = 0; j < 4; j++)
#pragma unroll
                for (int q = 0; q < 4; q++) Co[i][j][q] = 0.f;
        // AV: 8 steps u = s*2+p, double-buffered b frags
        {
            uint32_t bv[2][4];
            ldsm4(bv[0][0], bv[0][1], bv[0][2], bv[0][3], vaddr[0]);
#pragma unroll
            for (int u = 0; u < 8; u++) {
                const int cur = u & 1, nxt = cur ^ 1;
                if (u + 1 < 8) {
                    int s1 = (u + 1) >> 1, p1 = (u + 1) & 1;
                    ldsm4(bv[nxt][0], bv[nxt][1], bv[nxt][2], bv[nxt][3],
                          vaddr[p1] + s1 * 32);
                }
                const int s = u >> 1, p = u & 1;
#pragma unroll
                for (int i = 0; i < 2; i++) {
                    mma16(Co[i][2*p],   pf[i][s][0], pf[i][s][1], pf[i][s][2],
                          pf[i][s][3], bv[cur][0], bv[cur][1]);
                    mma16(Co[i][2*p+1], pf[i][s][0], pf[i][s][1], pf[i][s][2],
                          pf[i][s][3], bv[cur][2], bv[cur][3]);
                }
            }
        }
#pragma unroll
        for (int i = 0; i < 2; i++) {
            int ra = r0 + 16 * i + g;
#pragma unroll
            for (int j = 0; j < 4; j++) {
                int cl = hh * 32 + 8 * j + 2 * t;
                *(uint32_t*)(XN + ra * RSH + cl)       = pkhf(Co[i][j][0], Co[i][j][1]);
                *(uint32_t*)(XN + (ra + 8) * RSH + cl) = pkhf(Co[i][j][2], Co[i][j][3]);
            }
        }
    }
    CPA_WAIT0();
    __syncthreads();   // o in XN + Wout in WT1 + Wc in WT0

    // ---- out_proj: y = xw + o @ Wout^T + bout -> Kb ----
    {
        float C[2][4][4];
        gemm32<128>(XN, RSH, WT1, RSH, r0, c0, lane, C);
#pragma unroll
        for (int i = 0; i < 2; i++) {
            int ra = r0 + 16 * i + g;
#pragma unroll
            for (int j = 0; j < 4; j++) {
                int cl = c0 + 8 * j + 2 * t;
                float2 b2 = *(const float2*)(bout + cl);
                float2 xw0 = uphf(*(const uint32_t*)(XW + ra * RSH + cl));
                float2 xw1 = uphf(*(const uint32_t*)(XW + (ra + 8) * RSH + cl));
                *(uint32_t*)(Kb + ra * RSH + cl) =
                    pkhf(C[i][j][0] + b2.x + xw0.x, C[i][j][1] + b2.y + xw0.y);
                *(uint32_t*)(Kb + (ra + 8) * RSH + cl) =
                    pkhf(C[i][j][2] + b2.x + xw1.x, C[i][j][3] + b2.y + xw1.y);
            }
        }
    }
    __syncthreads();

    // ---- conv: Kb @ Wc^T + bc -> XN (fp16) ----
    {
        float C[2][4][4];
        gemm32<128>(Kb, RSH, WT0, RSH, r0, c0, lane, C);
#pragma unroll
        for (int i = 0; i < 2; i++) {
            int ra = r0 + 16 * i + g;
#pragma unroll
            for (int j = 0; j < 4; j++) {
                int cl = c0 + 8 * j + 2 * t;
                float2 b2 = *(const float2*)(bc + cl);
                *(uint32_t*)(XN + ra * RSH + cl) =
                    pkhf(C[i][j][0] + b2.x, C[i][j][1] + b2.y);
                *(uint32_t*)(XN + (ra + 8) * RSH + cl) =
                    pkhf(C[i][j][2] + b2.x, C[i][j][3] + b2.y);
            }
        }
    }
    __syncthreads();

    // ---- epilogue: out = conv(fp16) + x (exact fp32), coalesced ----
    float* outp = out + (size_t)bb * ((size_t)CCH * VOLS);
#pragma unroll
    for (int i = 0; i < 8; i++) {
        int c  = c0l + 32 * (i & 3);
        int tq = tq0 + 8 * (i >> 2);
        int dz = tq >> 2, dy = tq & 3;
        size_t gaddr = (size_t)c * VOLS + vox0 + dz * 4096 + dy * 64;
        float4 xv = *(const float4*)(xb + gaddr);
        const __half* src = XN + (tq * 4) * RSH + c;
        float4 v = { __half2float(src[0])       + xv.x,
                     __half2float(src[RSH])     + xv.y,
                     __half2float(src[2 * RSH]) + xv.z,
                     __half2float(src[3 * RSH]) + xv.w };
        *(float4*)(outp + gaddr) = v;
    }
}

static const int SMEM_BYTES = 210944;

extern "C" void kernel_launch(void* const* d_in, const int* in_sizes, int n_in,
                              void* d_out, int out_size) {
    const float* x    = (const float*)d_in[0];
    const float* ln_g = (const float*)d_in[1];
    const float* ln_b = (const float*)d_in[2];
    const float* Win  = (const float*)d_in[3];
    const float* bin  = (const float*)d_in[4];
    const float* Wout = (const float*)d_in[5];
    const float* bout = (const float*)d_in[6];
    const float* Wc   = (const float*)d_in[7];
    const float* bc   = (const float*)d_in[8];
    float* out = (float*)d_out;

    prep_weights<<<320, 256>>>(Win, Wout, Wc);

    cudaFuncSetAttribute(win_attn_kernel,
                         cudaFuncAttributeMaxDynamicSharedMemorySize, SMEM_BYTES);
    win_attn_kernel<<<4096, 512, SMEM_BYTES>>>(x, ln_g, ln_b, bin, bout, bc, out);
}